// round 9
// baseline (speedup 1.0000x reference)
#include <cuda_runtime.h>
#include <cuda_bf16.h>
#include <cstdint>

// Problem constants (fixed by setup_inputs)
#define BB   16
#define TT   2048
#define FF   64
#define AA   48
#define BT   128
#define NTHREADS 128
#define WSTRIDE  68
#define MAXWIN   (BT + AA)            // 176

// SMEM byte layout: 4 W-fragment planes (8 KB each) + fp32 window
// Plane layout: [kk (0..3)][ntile-pair p (0..3)][lane][16B]
#define SM_W1H  0
#define SM_W1L  8192
#define SM_W2H  16384
#define SM_W2L  24576
#define SM_WINB 32768
#define SMEM_BYTES (SM_WINB + MAXWIN * WSTRIDE * 4)   // 80640 -> 2 CTAs/SM

// ---------------- helpers ----------------
static __device__ __forceinline__ float sigmoidf_fast(float x) {
    float e = __expf(-x);
    float r;
    asm("rcp.approx.f32 %0, %1;" : "=f"(r) : "f"(1.0f + e));
    return r;
}
static __device__ __forceinline__ uint32_t prmt_hi(float x0, float x1) {
    uint32_t r;
    asm("prmt.b32 %0, %1, %2, 0x7632;" : "=r"(r)
        : "r"(__float_as_uint(x0)), "r"(__float_as_uint(x1)));
    return r;
}
static __device__ __forceinline__ float truncf16(float x) {
    return __uint_as_float(__float_as_uint(x) & 0xffff0000u);
}
static __device__ __forceinline__ uint32_t cvt_lo2(float l0, float l1) {
    uint32_t r;
    asm("cvt.rn.bf16x2.f32 %0, %1, %2;" : "=r"(r) : "f"(l1), "f"(l0));
    return r;
}
static __device__ __forceinline__ void split2(float x0, float x1, uint32_t& h, uint32_t& l) {
    h = prmt_hi(x0, x1);
    l = cvt_lo2(x0 - truncf16(x0), x1 - truncf16(x1));
}
// m16n8k16 bf16 MMA, f32 accumulate in place.
// NOT volatile: pure register dataflow -> ptxas may schedule/interleave freely.
static __device__ __forceinline__ void mma_bf16(float* c, const uint32_t* a,
                                                uint32_t b0, uint32_t b1) {
    asm("mma.sync.aligned.m16n8k16.row.col.f32.bf16.bf16.f32 "
        "{%0,%1,%2,%3}, {%4,%5,%6,%7}, {%8,%9}, {%0,%1,%2,%3};"
        : "+f"(c[0]), "+f"(c[1]), "+f"(c[2]), "+f"(c[3])
        : "r"(a[0]), "r"(a[1]), "r"(a[2]), "r"(a[3]), "r"(b0), "r"(b1));
}
static __device__ __forceinline__ unsigned long long pack2(float x, float y) {
    unsigned long long r;
    asm("mov.b64 %0, {%1, %2};" : "=l"(r) : "f"(x), "f"(y));
    return r;
}
static __device__ __forceinline__ void unpack2(unsigned long long v, float& x, float& y) {
    asm("mov.b64 {%0, %1}, %2;" : "=f"(x), "=f"(y) : "l"(v));
}
static __device__ __forceinline__ void fma2(unsigned long long& d,
                                            unsigned long long a, unsigned long long b) {
    asm("fma.rn.f32x2 %0, %1, %2, %0;" : "+l"(d) : "l"(a), "l"(b));
}

// One logical GEMM: C[2][8][4] += A @ W (3-term bf16 split), TERM-MAJOR order:
// per kk, issue 16 independent AhBh, then 16 AlBh, then 16 AhBl. Dependent MMAs
// on one accumulator are 16 issues apart -> HMMA latency hidden.
static __device__ __forceinline__ void gemm_split(
    float C[2][8][4],
    const uint32_t Ah[2][4][4], const uint32_t Al[2][4][4],
    const char* smem, int offH, int offL, int lane)
{
    #pragma unroll
    for (int kk = 0; kk < 4; ++kk) {
        uint4 bh[4], bl[4];
        #pragma unroll
        for (int p = 0; p < 4; ++p) {
            bh[p] = *(const uint4*)(smem + offH + kk * 2048 + p * 512 + lane * 16);
            bl[p] = *(const uint4*)(smem + offL + kk * 2048 + p * 512 + lane * 16);
        }
        // term 1: Ah x Bh
        #pragma unroll
        for (int i = 0; i < 2; ++i)
            #pragma unroll
            for (int p = 0; p < 4; ++p) {
                mma_bf16(C[i][2 * p + 0], Ah[i][kk], bh[p].x, bh[p].y);
                mma_bf16(C[i][2 * p + 1], Ah[i][kk], bh[p].z, bh[p].w);
            }
        // term 2: Al x Bh
        #pragma unroll
        for (int i = 0; i < 2; ++i)
            #pragma unroll
            for (int p = 0; p < 4; ++p) {
                mma_bf16(C[i][2 * p + 0], Al[i][kk], bh[p].x, bh[p].y);
                mma_bf16(C[i][2 * p + 1], Al[i][kk], bh[p].z, bh[p].w);
            }
        // term 3: Ah x Bl
        #pragma unroll
        for (int i = 0; i < 2; ++i)
            #pragma unroll
            for (int p = 0; p < 4; ++p) {
                mma_bf16(C[i][2 * p + 0], Ah[i][kk], bl[p].x, bl[p].y);
                mma_bf16(C[i][2 * p + 1], Ah[i][kk], bl[p].z, bl[p].w);
            }
    }
}

__global__ __launch_bounds__(NTHREADS, 2)
void context_block_kernel(const float* __restrict__ he,
                          const float* __restrict__ W1,
                          const float* __restrict__ W2,
                          float* __restrict__ out)
{
    extern __shared__ char smem[];
    float* win = (float*)(smem + SM_WINB);

    const int tid  = threadIdx.x;
    const int wid  = tid >> 5;
    const int lane = tid & 31;
    const int gid  = lane >> 2;       // groupID (row within tile)
    const int tig  = lane & 3;        // thread-in-group (col pair)
    const int b    = blockIdx.x / (TT / BT);
    const int t0   = (blockIdx.x % (TT / BT)) * BT;

    // ---- Stage he window [base, t0+BT) ----
    const int base = (t0 - AA) > 0 ? (t0 - AA) : 0;
    const int nwin = t0 + BT - base;              // <= 176
    {
        const float4* heb = (const float4*)(he + ((size_t)b * TT) * FF);
        for (int i = tid; i < nwin * (FF / 4); i += NTHREADS) {
            int r = i >> 4;
            int c = i & 15;
            float4 v = heb[(size_t)(base + r) * (FF / 4) + c];
            *(float4*)&win[r * WSTRIDE + 4 * c] = v;
        }
    }

    // ---- Build W B-fragments (bf16 hi/lo), warp wid handles kk = wid ----
    {
        const int kk = wid;
        #pragma unroll
        for (int p = 0; p < 4; ++p) {
            uint32_t r1h[4], r1l[4], r2h[4], r2l[4];
            #pragma unroll
            for (int nt2 = 0; nt2 < 2; ++nt2) {
                int n = 8 * (2 * p + nt2) + gid;
                #pragma unroll
                for (int h = 0; h < 2; ++h) {
                    int k0 = 16 * kk + 2 * tig + 8 * h;
                    float a0 = W1[k0 * FF + n], a1 = W1[(k0 + 1) * FF + n];
                    split2(a0, a1, r1h[2 * nt2 + h], r1l[2 * nt2 + h]);
                    float c0 = W2[k0 * FF + n], c1 = W2[(k0 + 1) * FF + n];
                    split2(c0, c1, r2h[2 * nt2 + h], r2l[2 * nt2 + h]);
                }
            }
            int o = kk * 2048 + p * 512 + lane * 16;
            *(uint4*)(smem + SM_W1H + o) = make_uint4(r1h[0], r1h[1], r1h[2], r1h[3]);
            *(uint4*)(smem + SM_W1L + o) = make_uint4(r1l[0], r1l[1], r1l[2], r1l[3]);
            *(uint4*)(smem + SM_W2H + o) = make_uint4(r2h[0], r2h[1], r2h[2], r2h[3]);
            *(uint4*)(smem + SM_W2L + o) = make_uint4(r2l[0], r2l[1], r2l[2], r2l[3]);
        }
    }
    __syncthreads();    // the ONLY block sync

    // ---- per-thread row bookkeeping (4 MMA rows, q = h + 2i) ----
    int trow[4], Lr[4];
    #pragma unroll
    for (int q = 0; q < 4; ++q) {
        trow[q] = t0 + 32 * wid + gid + 8 * (q & 1) + 16 * (q >> 1);
        int tm = (trow[q] > 1) ? trow[q] : 1;
        Lr[q] = (AA < tm) ? AA : tm;
    }
    const int jmax = t0 + BT - 1;

    // ---- initial A fragments ----
    uint32_t Ah[2][4][4], Al[2][4][4];
    #pragma unroll
    for (int i = 0; i < 2; ++i) {
        const float* w0 = win + (trow[2 * i + 0] - base) * WSTRIDE;
        const float* w1 = win + (trow[2 * i + 1] - base) * WSTRIDE;
        #pragma unroll
        for (int kk = 0; kk < 4; ++kk) {
            float2 p00 = *(const float2*)(w0 + 16 * kk + 2 * tig);
            float2 p10 = *(const float2*)(w1 + 16 * kk + 2 * tig);
            float2 p01 = *(const float2*)(w0 + 16 * kk + 2 * tig + 8);
            float2 p11 = *(const float2*)(w1 + 16 * kk + 2 * tig + 8);
            split2(p00.x, p00.y, Ah[i][kk][0], Al[i][kk][0]);
            split2(p10.x, p10.y, Ah[i][kk][1], Al[i][kk][1]);
            split2(p01.x, p01.y, Ah[i][kk][2], Al[i][kk][2]);
            split2(p11.x, p11.y, Ah[i][kk][3], Al[i][kk][3]);
        }
    }

    float sc[AA];

    // ================= 48-step scan (all-register recurrence) =================
    #pragma unroll 1
    for (int a = 0; a < AA; ++a) {
        float C[2][8][4];

        // ---- GEMM1 ----
        #pragma unroll
        for (int i = 0; i < 2; ++i)
            #pragma unroll
            for (int n = 0; n < 8; ++n)
                #pragma unroll
                for (int r = 0; r < 4; ++r) C[i][n][r] = 0.0f;
        gemm_split(C, Ah, Al, smem, SM_W1H, SM_W1L, lane);

        // ---- sigma + in-register repack ----
        #pragma unroll
        for (int i = 0; i < 2; ++i) {
            #pragma unroll
            for (int kk = 0; kk < 4; ++kk) {
                float s0 = sigmoidf_fast(C[i][2 * kk][0]);
                float s1 = sigmoidf_fast(C[i][2 * kk][1]);
                float s2 = sigmoidf_fast(C[i][2 * kk][2]);
                float s3 = sigmoidf_fast(C[i][2 * kk][3]);
                float s4 = sigmoidf_fast(C[i][2 * kk + 1][0]);
                float s5 = sigmoidf_fast(C[i][2 * kk + 1][1]);
                float s6 = sigmoidf_fast(C[i][2 * kk + 1][2]);
                float s7 = sigmoidf_fast(C[i][2 * kk + 1][3]);
                split2(s0, s1, Ah[i][kk][0], Al[i][kk][0]);
                split2(s2, s3, Ah[i][kk][1], Al[i][kk][1]);
                split2(s4, s5, Ah[i][kk][2], Al[i][kk][2]);
                split2(s6, s7, Ah[i][kk][3], Al[i][kk][3]);
            }
        }

        // ---- GEMM2 ----
        #pragma unroll
        for (int i = 0; i < 2; ++i)
            #pragma unroll
            for (int n = 0; n < 8; ++n)
                #pragma unroll
                for (int r = 0; r < 4; ++r) C[i][n][r] = 0.0f;
        gemm_split(C, Ah, Al, smem, SM_W2H, SM_W2L, lane);

        // ---- scores ----
        int joff[4];
        #pragma unroll
        for (int q = 0; q < 4; ++q) {
            int j = trow[q] - Lr[q] + a;
            if (j < 0) j = 0;
            if (j > jmax) j = jmax;
            joff[q] = (j - base) * WSTRIDE;
        }
        float s[4] = {0.0f, 0.0f, 0.0f, 0.0f};
        #pragma unroll
        for (int i = 0; i < 2; ++i) {
            const float* gA = win + joff[2 * i + 0] + 2 * tig;
            const float* gB = win + joff[2 * i + 1] + 2 * tig;
            #pragma unroll
            for (int n = 0; n < 8; ++n) {
                float2 g0 = *(const float2*)(gA + 8 * n);
                float2 g1 = *(const float2*)(gB + 8 * n);
                s[2 * i + 0] = fmaf(sigmoidf_fast(C[i][n][0]), g0.x, s[2 * i + 0]);
                s[2 * i + 0] = fmaf(sigmoidf_fast(C[i][n][1]), g0.y, s[2 * i + 0]);
                s[2 * i + 1] = fmaf(sigmoidf_fast(C[i][n][2]), g1.x, s[2 * i + 1]);
                s[2 * i + 1] = fmaf(sigmoidf_fast(C[i][n][3]), g1.y, s[2 * i + 1]);
            }
        }
        // quad transpose-reduce
        {
            int q1 = tig & 1, q2b = (tig >> 1) & 1;
            float ma = q1 ? s[1] : s[0];
            float oa = q1 ? s[0] : s[1];
            float mb = q1 ? s[3] : s[2];
            float ob = q1 ? s[2] : s[3];
            float ta = ma + __shfl_xor_sync(0xffffffffu, oa, 1);
            float tb = mb + __shfl_xor_sync(0xffffffffu, ob, 1);
            float m2 = q2b ? tb : ta;
            float o2 = q2b ? ta : tb;
            sc[a] = m2 + __shfl_xor_sync(0xffffffffu, o2, 2);
        }
    }

    // ================= softmax + context (thread row = gid + 8*tig) =================
    const int t = t0 + 32 * wid + gid + 8 * tig;
    const int tm = (t > 1) ? t : 1;
    const int L = (AA < tm) ? AA : tm;

    float m = -1e30f;
    for (int a = 0; a < L; ++a) m = fmaxf(m, sc[a]);

    unsigned long long ctx2[FF / 2];
    #pragma unroll
    for (int j = 0; j < FF / 2; ++j) ctx2[j] = 0ull;

    float ssum = 0.0f;
    for (int a = 0; a < L; ++a) {
        float w = __expf(sc[a] - m);
        ssum += w;
        unsigned long long w2 = pack2(w, w);
        int j = t - L + a;
        if (j < 0) j = 0;
        const ulonglong2* g2 = (const ulonglong2*)&win[(j - base) * WSTRIDE];
        #pragma unroll
        for (int i = 0; i < FF / 4; ++i) {
            ulonglong2 gv = g2[i];
            fma2(ctx2[2 * i + 0], w2, gv.x);
            fma2(ctx2[2 * i + 1], w2, gv.y);
        }
    }

    float inv;
    asm("rcp.approx.f32 %0, %1;" : "=f"(inv) : "f"(ssum));
    inv = inv * (2.0f - ssum * inv);   // Newton step -> full fp32 accuracy

    float4* outp = (float4*)(out + ((size_t)b * TT + t) * FF);
    #pragma unroll
    for (int c = 0; c < FF / 4; ++c) {
        float x0, y0, x1, y1;
        unpack2(ctx2[2 * c + 0], x0, y0);
        unpack2(ctx2[2 * c + 1], x1, y1);
        float4 v;
        v.x = x0 * inv; v.y = y0 * inv; v.z = x1 * inv; v.w = y1 * inv;
        outp[c] = v;
    }
}

extern "C" void kernel_launch(void* const* d_in, const int* in_sizes, int n_in,
                              void* d_out, int out_size)
{
    const float* he = (const float*)d_in[0];
    const float* W1 = (const float*)d_in[1];
    const float* W2 = (const float*)d_in[2];
    float* out = (float*)d_out;

    cudaFuncSetAttribute(context_block_kernel,
                         cudaFuncAttributeMaxDynamicSharedMemorySize, SMEM_BYTES);

    const int grid = (BB * TT) / BT;   // 256 blocks
    context_block_kernel<<<grid, NTHREADS, SMEM_BYTES>>>(he, W1, W2, out);
}

// round 13
// speedup vs baseline: 1.1267x; 1.1267x over previous
#include <cuda_runtime.h>
#include <cuda_bf16.h>
#include <cstdint>

// Problem constants (fixed by setup_inputs)
#define BB   16
#define TT   2048
#define FF   64
#define AA   48
#define BT   128
#define NTHREADS 128
#define WSTRIDE  68
#define MAXWIN   (BT + AA)            // 176

// SMEM byte layout: 4 W-fragment planes (8 KB each) + fp32 window
// Plane layout: [kk (0..3)][ntile-pair p (0..3)][lane][16B]
#define SM_W1H  0
#define SM_W1L  8192
#define SM_W2H  16384
#define SM_W2L  24576
#define SM_WINB 32768
#define SMEM_BYTES (SM_WINB + MAXWIN * WSTRIDE * 4)   // 80640 -> 2 CTAs/SM

// ---------------- helpers ----------------
static __device__ __forceinline__ float sigmoidf_fast(float x) {
    float e = __expf(-x);
    float r;
    asm("rcp.approx.f32 %0, %1;" : "=f"(r) : "f"(1.0f + e));
    return r;
}
static __device__ __forceinline__ uint32_t prmt_hi(float x0, float x1) {
    uint32_t r;
    asm("prmt.b32 %0, %1, %2, 0x7632;" : "=r"(r)
        : "r"(__float_as_uint(x0)), "r"(__float_as_uint(x1)));
    return r;
}
static __device__ __forceinline__ float truncf16(float x) {
    return __uint_as_float(__float_as_uint(x) & 0xffff0000u);
}
static __device__ __forceinline__ uint32_t cvt_lo2(float l0, float l1) {
    uint32_t r;
    asm("cvt.rn.bf16x2.f32 %0, %1, %2;" : "=r"(r) : "f"(l1), "f"(l0));
    return r;
}
static __device__ __forceinline__ void split2(float x0, float x1, uint32_t& h, uint32_t& l) {
    h = prmt_hi(x0, x1);
    l = cvt_lo2(x0 - truncf16(x0), x1 - truncf16(x1));
}
// m16n8k16 bf16 MMA, f32 accumulate in place. volatile: pin my issue order.
static __device__ __forceinline__ void mma_bf16(float* c, const uint32_t* a,
                                                uint32_t b0, uint32_t b1) {
    asm volatile("mma.sync.aligned.m16n8k16.row.col.f32.bf16.bf16.f32 "
                 "{%0,%1,%2,%3}, {%4,%5,%6,%7}, {%8,%9}, {%0,%1,%2,%3};"
                 : "+f"(c[0]), "+f"(c[1]), "+f"(c[2]), "+f"(c[3])
                 : "r"(a[0]), "r"(a[1]), "r"(a[2]), "r"(a[3]), "r"(b0), "r"(b1));
}
static __device__ __forceinline__ unsigned long long pack2(float x, float y) {
    unsigned long long r;
    asm("mov.b64 %0, {%1, %2};" : "=l"(r) : "f"(x), "f"(y));
    return r;
}
static __device__ __forceinline__ void unpack2(unsigned long long v, float& x, float& y) {
    asm("mov.b64 {%0, %1}, %2;" : "=f"(x), "=f"(y) : "l"(v));
}
static __device__ __forceinline__ void fma2(unsigned long long& d,
                                            unsigned long long a, unsigned long long b) {
    asm("fma.rn.f32x2 %0, %1, %2, %0;" : "+l"(d) : "l"(a), "l"(b));
}

// 12 MMAs for one (kk, p) pair: 4 independent accumulator chains, term-major
// within the group (dependent distance 4). B live = 8 regs only.
static __device__ __forceinline__ void mma_group(
    float* c00, float* c01, float* c10, float* c11,
    const uint32_t* a0h, const uint32_t* a0l,
    const uint32_t* a1h, const uint32_t* a1l,
    const uint4& bh, const uint4& bl)
{
    mma_bf16(c00, a0h, bh.x, bh.y);
    mma_bf16(c01, a0h, bh.z, bh.w);
    mma_bf16(c10, a1h, bh.x, bh.y);
    mma_bf16(c11, a1h, bh.z, bh.w);
    mma_bf16(c00, a0l, bh.x, bh.y);
    mma_bf16(c01, a0l, bh.z, bh.w);
    mma_bf16(c10, a1l, bh.x, bh.y);
    mma_bf16(c11, a1l, bh.z, bh.w);
    mma_bf16(c00, a0h, bl.x, bl.y);
    mma_bf16(c01, a0h, bl.z, bl.w);
    mma_bf16(c10, a1h, bl.x, bl.y);
    mma_bf16(c11, a1h, bl.z, bl.w);
}

// Full GEMM (8 n-tiles): C[2][8][4] += A @ W
static __device__ __forceinline__ void gemm_full(
    float C[2][8][4],
    const uint32_t Ah[2][4][4], const uint32_t Al[2][4][4],
    const char* smem, int offH, int offL, int lane)
{
    #pragma unroll
    for (int kk = 0; kk < 4; ++kk) {
        #pragma unroll
        for (int p = 0; p < 4; ++p) {
            int o = kk * 2048 + p * 512 + lane * 16;
            uint4 bh = *(const uint4*)(smem + offH + o);
            uint4 bl = *(const uint4*)(smem + offL + o);
            mma_group(C[0][2 * p], C[0][2 * p + 1], C[1][2 * p], C[1][2 * p + 1],
                      Ah[0][kk], Al[0][kk], Ah[1][kk], Al[1][kk], bh, bl);
        }
    }
}

// Half GEMM (2 n-tiles, p = pbase..pbase+1): C[2][4][4] += A @ W
static __device__ __forceinline__ void gemm_half(
    float C[2][4][4],
    const uint32_t Ah[2][4][4], const uint32_t Al[2][4][4],
    const char* smem, int offH, int offL, int lane, int pbase)
{
    #pragma unroll
    for (int kk = 0; kk < 4; ++kk) {
        #pragma unroll
        for (int pl = 0; pl < 2; ++pl) {
            int o = kk * 2048 + (pbase + pl) * 512 + lane * 16;
            uint4 bh = *(const uint4*)(smem + offH + o);
            uint4 bl = *(const uint4*)(smem + offL + o);
            mma_group(C[0][2 * pl], C[0][2 * pl + 1], C[1][2 * pl], C[1][2 * pl + 1],
                      Ah[0][kk], Al[0][kk], Ah[1][kk], Al[1][kk], bh, bl);
        }
    }
}

__global__ __launch_bounds__(NTHREADS, 2)
void context_block_kernel(const float* __restrict__ he,
                          const float* __restrict__ W1,
                          const float* __restrict__ W2,
                          float* __restrict__ out)
{
    extern __shared__ char smem[];
    float* win = (float*)(smem + SM_WINB);

    const int tid  = threadIdx.x;
    const int wid  = tid >> 5;
    const int lane = tid & 31;
    const int gid  = lane >> 2;       // groupID (row within tile)
    const int tig  = lane & 3;        // thread-in-group (col pair)
    const int b    = blockIdx.x / (TT / BT);
    const int t0   = (blockIdx.x % (TT / BT)) * BT;

    // ---- Stage he window [base, t0+BT) ----
    const int base = (t0 - AA) > 0 ? (t0 - AA) : 0;
    const int nwin = t0 + BT - base;              // <= 176
    {
        const float4* heb = (const float4*)(he + ((size_t)b * TT) * FF);
        for (int i = tid; i < nwin * (FF / 4); i += NTHREADS) {
            int r = i >> 4;
            int c = i & 15;
            float4 v = heb[(size_t)(base + r) * (FF / 4) + c];
            *(float4*)&win[r * WSTRIDE + 4 * c] = v;
        }
    }

    // ---- Build W B-fragments (bf16 hi/lo), warp wid handles kk = wid ----
    {
        const int kk = wid;
        #pragma unroll
        for (int p = 0; p < 4; ++p) {
            uint32_t r1h[4], r1l[4], r2h[4], r2l[4];
            #pragma unroll
            for (int nt2 = 0; nt2 < 2; ++nt2) {
                int n = 8 * (2 * p + nt2) + gid;
                #pragma unroll
                for (int h = 0; h < 2; ++h) {
                    int k0 = 16 * kk + 2 * tig + 8 * h;
                    float a0 = W1[k0 * FF + n], a1 = W1[(k0 + 1) * FF + n];
                    split2(a0, a1, r1h[2 * nt2 + h], r1l[2 * nt2 + h]);
                    float c0 = W2[k0 * FF + n], c1 = W2[(k0 + 1) * FF + n];
                    split2(c0, c1, r2h[2 * nt2 + h], r2l[2 * nt2 + h]);
                }
            }
            int o = kk * 2048 + p * 512 + lane * 16;
            *(uint4*)(smem + SM_W1H + o) = make_uint4(r1h[0], r1h[1], r1h[2], r1h[3]);
            *(uint4*)(smem + SM_W1L + o) = make_uint4(r1l[0], r1l[1], r1l[2], r1l[3]);
            *(uint4*)(smem + SM_W2H + o) = make_uint4(r2h[0], r2h[1], r2h[2], r2h[3]);
            *(uint4*)(smem + SM_W2L + o) = make_uint4(r2l[0], r2l[1], r2l[2], r2l[3]);
        }
    }
    __syncthreads();    // the ONLY block sync

    // ---- per-thread row bookkeeping (4 MMA rows, q = h + 2i) ----
    int trow[4], Lr[4];
    #pragma unroll
    for (int q = 0; q < 4; ++q) {
        trow[q] = t0 + 32 * wid + gid + 8 * (q & 1) + 16 * (q >> 1);
        int tm = (trow[q] > 1) ? trow[q] : 1;
        Lr[q] = (AA < tm) ? AA : tm;
    }
    const int jmax = t0 + BT - 1;

    // ---- initial A fragments ----
    uint32_t Ah[2][4][4], Al[2][4][4];
    #pragma unroll
    for (int i = 0; i < 2; ++i) {
        const float* w0 = win + (trow[2 * i + 0] - base) * WSTRIDE;
        const float* w1 = win + (trow[2 * i + 1] - base) * WSTRIDE;
        #pragma unroll
        for (int kk = 0; kk < 4; ++kk) {
            float2 p00 = *(const float2*)(w0 + 16 * kk + 2 * tig);
            float2 p10 = *(const float2*)(w1 + 16 * kk + 2 * tig);
            float2 p01 = *(const float2*)(w0 + 16 * kk + 2 * tig + 8);
            float2 p11 = *(const float2*)(w1 + 16 * kk + 2 * tig + 8);
            split2(p00.x, p00.y, Ah[i][kk][0], Al[i][kk][0]);
            split2(p10.x, p10.y, Ah[i][kk][1], Al[i][kk][1]);
            split2(p01.x, p01.y, Ah[i][kk][2], Al[i][kk][2]);
            split2(p11.x, p11.y, Ah[i][kk][3], Al[i][kk][3]);
        }
    }

    float sc[AA];
    float C1[2][8][4];

    // ---- pre-loop: C1 = H0 @ W1 ----
    #pragma unroll
    for (int i = 0; i < 2; ++i)
        #pragma unroll
        for (int n = 0; n < 8; ++n)
            #pragma unroll
            for (int r = 0; r < 4; ++r) C1[i][n][r] = 0.0f;
    gemm_full(C1, Ah, Al, smem, SM_W1H, SM_W1L, lane);

    // ================= 48-step scan (rotated: GEMM1[a+1] overlaps epilogue) ====
    #pragma unroll 1
    for (int a = 0; a < AA; ++a) {
        // ---- sigma(C1) + in-register repack -> A (H for this step's GEMM2) ----
        #pragma unroll
        for (int i = 0; i < 2; ++i) {
            #pragma unroll
            for (int kk = 0; kk < 4; ++kk) {
                float s0 = sigmoidf_fast(C1[i][2 * kk][0]);
                float s1 = sigmoidf_fast(C1[i][2 * kk][1]);
                float s2 = sigmoidf_fast(C1[i][2 * kk][2]);
                float s3 = sigmoidf_fast(C1[i][2 * kk][3]);
                float s4 = sigmoidf_fast(C1[i][2 * kk + 1][0]);
                float s5 = sigmoidf_fast(C1[i][2 * kk + 1][1]);
                float s6 = sigmoidf_fast(C1[i][2 * kk + 1][2]);
                float s7 = sigmoidf_fast(C1[i][2 * kk + 1][3]);
                split2(s0, s1, Ah[i][kk][0], Al[i][kk][0]);
                split2(s2, s3, Ah[i][kk][1], Al[i][kk][1]);
                split2(s4, s5, Ah[i][kk][2], Al[i][kk][2]);
                split2(s6, s7, Ah[i][kk][3], Al[i][kk][3]);
            }
        }

        // ---- issue GEMM1 for step a+1 (off the score path; feeds tensor pipe
        //      while this step's epilogues run) ----
        #pragma unroll
        for (int i = 0; i < 2; ++i)
            #pragma unroll
            for (int n = 0; n < 8; ++n)
                #pragma unroll
                for (int r = 0; r < 4; ++r) C1[i][n][r] = 0.0f;
        gemm_full(C1, Ah, Al, smem, SM_W1H, SM_W1L, lane);

        // ---- score row offsets ----
        int joff[4];
        #pragma unroll
        for (int q = 0; q < 4; ++q) {
            int j = trow[q] - Lr[q] + a;
            if (j < 0) j = 0;
            if (j > jmax) j = jmax;
            joff[q] = (j - base) * WSTRIDE;
        }
        float s[4] = {0.0f, 0.0f, 0.0f, 0.0f};

        // ---- GEMM2 in two n-halves; epilogue of each half overlaps the
        //      still-draining MMA stream ----
        #pragma unroll
        for (int h = 0; h < 2; ++h) {
            float C2[2][4][4];
            #pragma unroll
            for (int i = 0; i < 2; ++i)
                #pragma unroll
                for (int n = 0; n < 4; ++n)
                    #pragma unroll
                    for (int r = 0; r < 4; ++r) C2[i][n][r] = 0.0f;
            gemm_half(C2, Ah, Al, smem, SM_W2H, SM_W2L, lane, 2 * h);

            #pragma unroll
            for (int i = 0; i < 2; ++i) {
                const float* gA = win + joff[2 * i + 0] + 2 * tig + 32 * h;
                const float* gB = win + joff[2 * i + 1] + 2 * tig + 32 * h;
                #pragma unroll
                for (int nl = 0; nl < 4; ++nl) {
                    float2 g0 = *(const float2*)(gA + 8 * nl);
                    float2 g1 = *(const float2*)(gB + 8 * nl);
                    s[2 * i + 0] = fmaf(sigmoidf_fast(C2[i][nl][0]), g0.x, s[2 * i + 0]);
                    s[2 * i + 0] = fmaf(sigmoidf_fast(C2[i][nl][1]), g0.y, s[2 * i + 0]);
                    s[2 * i + 1] = fmaf(sigmoidf_fast(C2[i][nl][2]), g1.x, s[2 * i + 1]);
                    s[2 * i + 1] = fmaf(sigmoidf_fast(C2[i][nl][3]), g1.y, s[2 * i + 1]);
                }
            }
        }

        // ---- quad transpose-reduce: lane tig==q gets row (gid + 8q) ----
        {
            int q1 = tig & 1, q2b = (tig >> 1) & 1;
            float ma = q1 ? s[1] : s[0];
            float oa = q1 ? s[0] : s[1];
            float mb = q1 ? s[3] : s[2];
            float ob = q1 ? s[2] : s[3];
            float ta = ma + __shfl_xor_sync(0xffffffffu, oa, 1);
            float tb = mb + __shfl_xor_sync(0xffffffffu, ob, 1);
            float m2 = q2b ? tb : ta;
            float o2 = q2b ? ta : tb;
            sc[a] = m2 + __shfl_xor_sync(0xffffffffu, o2, 2);
        }
    }

    // ================= softmax + context (thread row = gid + 8*tig) =================
    const int t = t0 + 32 * wid + gid + 8 * tig;
    const int tm = (t > 1) ? t : 1;
    const int L = (AA < tm) ? AA : tm;

    float m = -1e30f;
    for (int a = 0; a < L; ++a) m = fmaxf(m, sc[a]);

    unsigned long long ctx2[FF / 2];
    #pragma unroll
    for (int j = 0; j < FF / 2; ++j) ctx2[j] = 0ull;

    float ssum = 0.0f;
    for (int a = 0; a < L; ++a) {
        float w = __expf(sc[a] - m);
        ssum += w;
        unsigned long long w2 = pack2(w, w);
        int j = t - L + a;
        if (j < 0) j = 0;
        const ulonglong2* g2 = (const ulonglong2*)&win[(j - base) * WSTRIDE];
        #pragma unroll
        for (int i = 0; i < FF / 4; ++i) {
            ulonglong2 gv = g2[i];
            fma2(ctx2[2 * i + 0], w2, gv.x);
            fma2(ctx2[2 * i + 1], w2, gv.y);
        }
    }

    float inv;
    asm("rcp.approx.f32 %0, %1;" : "=f"(inv) : "f"(ssum));
    inv = inv * (2.0f - ssum * inv);   // Newton step -> full fp32 accuracy

    float4* outp = (float4*)(out + ((size_t)b * TT + t) * FF);
    #pragma unroll
    for (int c = 0; c < FF / 4; ++c) {
        float x0, y0, x1, y1;
        unpack2(ctx2[2 * c + 0], x0, y0);
        unpack2(ctx2[2 * c + 1], x1, y1);
        float4 v;
        v.x = x0 * inv; v.y = y0 * inv; v.z = x1 * inv; v.w = y1 * inv;
        outp[c] = v;
    }
}

extern "C" void kernel_launch(void* const* d_in, const int* in_sizes, int n_in,
                              void* d_out, int out_size)
{
    const float* he = (const float*)d_in[0];
    const float* W1 = (const float*)d_in[1];
    const float* W2 = (const float*)d_in[2];
    float* out = (float*)d_out;

    cudaFuncSetAttribute(context_block_kernel,
                         cudaFuncAttributeMaxDynamicSharedMemorySize, SMEM_BYTES);

    const int grid = (BB * TT) / BT;   // 256 blocks
    context_block_kernel<<<grid, NTHREADS, SMEM_BYTES>>>(he, W1, W2, out);
}